// round 2
// baseline (speedup 1.0000x reference)
#include <cuda_runtime.h>
#include <cstdint>

// Problem constants (fixed per reference)
#define LL   50      // sequence length
#define DD   64      // per-table embedding dim
#define EE   128     // concat embedding dim (2*DD)
#define UU   256     // hidden units
#define NT   512     // threads per CTA

// Shared memory layout (floats):
//  sW2q : 128*256   folded weight W2q[d][u] = W_hide[128+d][u] + q[d]*W_hide[256+d][u]
//  sk   : 50*128    K tile (gathered embeddings)
//  sq   : 128       query embedding
//  sAbh : 256       b_hide[u] + sum_d q[d]*W_hide[d][u]
//  spA  : 256       partial A (upper half of d)
//  sWout: 256       W_out
//  sout : 128       output accumulator
//  + sactive[64] int, scnt int
#define SMEM_FLOATS (128*256 + LL*EE + EE + UU + UU + UU + EE)
#define SMEM_BYTES  (SMEM_FLOATS*4 + 64*4 + 16)

extern "C" __global__ void __launch_bounds__(NT, 1)
din_fused_kernel(const int*      __restrict__ qid_item,
                 const int*      __restrict__ qid_cate,
                 const int*      __restrict__ sid_item,
                 const int*      __restrict__ sid_cate,
                 const int*      __restrict__ mask,     // bool widened to 4-byte (int32 or f32): nonzero == true
                 const float*    __restrict__ emb_item,
                 const float*    __restrict__ emb_cate,
                 const float*    __restrict__ W_hide,
                 const float*    __restrict__ b_hide,
                 const float*    __restrict__ W_out,
                 const float*    __restrict__ b_out,
                 float*          __restrict__ out)
{
    extern __shared__ float smem[];
    float* sW2q  = smem;                    // 128*256
    float* sk    = sW2q + 128*256;          // 50*128
    float* sq    = sk   + LL*EE;            // 128
    float* sAbh  = sq   + EE;               // 256
    float* spA   = sAbh + UU;               // 256
    float* sWout = spA  + UU;               // 256
    float* sout  = sWout+ UU;               // 128
    int*   sactive = (int*)(sout + EE);     // 64
    int*   scnt    = sactive + 64;

    const int b   = blockIdx.x;
    const int tid = threadIdx.x;

    if (tid == 0) *scnt = 0;
    __syncthreads();

    // ---------------- Phase 1: gathers, mask compaction, small loads ----------
    const int qi = qid_item[b];
    const int qc = qid_cate[b];
    if (tid < EE) {
        sq[tid]   = (tid < DD) ? emb_item[(size_t)qi*DD + tid]
                               : emb_cate[(size_t)qc*DD + (tid - DD)];
        sout[tid] = 0.f;
    }
    if (tid < UU) sWout[tid] = W_out[tid];
    if (tid < LL) {
        if (mask[(size_t)b*LL + tid] != 0) {
            int p = atomicAdd(scnt, 1);
            sactive[p] = tid;
        }
    }
    for (int idx = tid; idx < LL*EE; idx += NT) {
        int l = idx >> 7;          // /128
        int e = idx & 127;
        sk[idx] = (e < DD) ? emb_item[(size_t)sid_item[(size_t)b*LL + l]*DD + e]
                           : emb_cate[(size_t)sid_cate[(size_t)b*LL + l]*DD + (e - DD)];
    }
    __syncthreads();

    // ---------------- Phase 2: build Abh and folded weight W2q ----------------
    {
        const int u    = tid & (UU - 1);
        const int half = tid >> 8;          // 0 or 1
        const int d0   = half * 64;
        const float* Wq = W_hide + u;                       // rows [0,128)
        const float* Wk = W_hide + (size_t)128*UU + u;      // rows [128,256)
        const float* Wp = W_hide + (size_t)256*UU + u;      // rows [256,384)
        float a = 0.f;
        #pragma unroll 8
        for (int dd = 0; dd < 64; dd++) {
            const int d  = d0 + dd;
            const float qd = sq[d];
            a += qd * Wq[(size_t)d*UU];
            sW2q[d*UU + u] = Wk[(size_t)d*UU] + qd * Wp[(size_t)d*UU];
        }
        if (half == 0) sAbh[u] = a; else spA[u] = a;
    }
    __syncthreads();
    if (tid < UU) sAbh[tid] = sAbh[tid] + spA[tid] + b_hide[tid];
    __syncthreads();

    // ---------------- Phase 3: mainloop over active l's ----------------------
    // warp w handles active indices [4w, 4w+4); 16 warps * 4 = 64 >= nact always
    const int nact = *scnt;
    const int warp = tid >> 5;
    const int lane = tid & 31;
    const int i0   = warp * 4;

    if (i0 < nact) {
        int nl = nact - i0; if (nl > 4) nl = 4;
        const int l0 = sactive[i0];
        const int l1 = sactive[(nl > 1) ? i0 + 1 : i0];
        const int l2 = sactive[(nl > 2) ? i0 + 2 : i0];
        const int l3 = sactive[(nl > 3) ? i0 + 3 : i0];
        const float* k0 = sk + l0*EE;
        const float* k1 = sk + l1*EE;
        const float* k2 = sk + l2*EE;
        const float* k3 = sk + l3*EE;

        const int ub = lane * 8;   // this lane's 8 hidden units
        float acc0[8], acc1[8], acc2[8], acc3[8];
        #pragma unroll
        for (int t = 0; t < 8; t++) {
            const float a = sAbh[ub + t];
            acc0[t] = a; acc1[t] = a; acc2[t] = a; acc3[t] = a;
        }

        #pragma unroll 2
        for (int d = 0; d < EE; d++) {
            const float4 wa = *(const float4*)(sW2q + d*UU + ub);
            const float4 wb = *(const float4*)(sW2q + d*UU + ub + 4);
            const float kd0 = k0[d], kd1 = k1[d], kd2 = k2[d], kd3 = k3[d];
            const float w[8] = {wa.x, wa.y, wa.z, wa.w, wb.x, wb.y, wb.z, wb.w};
            #pragma unroll
            for (int t = 0; t < 8; t++) {
                acc0[t] += kd0 * w[t];
                acc1[t] += kd1 * w[t];
                acc2[t] += kd2 * w[t];
                acc3[t] += kd3 * w[t];
            }
        }

        // relu + dot with W_out (per-lane partial over its 8 units)
        float s0 = 0.f, s1 = 0.f, s2 = 0.f, s3 = 0.f;
        #pragma unroll
        for (int t = 0; t < 8; t++) {
            const float wo = sWout[ub + t];
            s0 += fmaxf(acc0[t], 0.f) * wo;
            s1 += fmaxf(acc1[t], 0.f) * wo;
            s2 += fmaxf(acc2[t], 0.f) * wo;
            s3 += fmaxf(acc3[t], 0.f) * wo;
        }
        // warp-wide reduce
        #pragma unroll
        for (int off = 16; off > 0; off >>= 1) {
            s0 += __shfl_xor_sync(0xffffffffu, s0, off);
            s1 += __shfl_xor_sync(0xffffffffu, s1, off);
            s2 += __shfl_xor_sync(0xffffffffu, s2, off);
            s3 += __shfl_xor_sync(0xffffffffu, s3, off);
        }
        const float bo = b_out[0];
        s0 += bo;                                 // mask==1 for active l's
        s1 = (nl > 1) ? s1 + bo : 0.f;            // duplicated l's contribute 0
        s2 = (nl > 2) ? s2 + bo : 0.f;
        s3 = (nl > 3) ? s3 + bo : 0.f;

        // weighted sum into sout: lane covers e = lane*4 .. lane*4+3
        const int e0 = lane * 4;
        #pragma unroll
        for (int t = 0; t < 4; t++) {
            const int e = e0 + t;
            const float v = s0*k0[e] + s1*k1[e] + s2*k2[e] + s3*k3[e];
            atomicAdd(&sout[e], v);
        }
    }
    __syncthreads();

    // ---------------- Phase 4: write output -----------------------------------
    if (tid < EE) out[(size_t)b*EE + tid] = sout[tid];
}

extern "C" void kernel_launch(void* const* d_in, const int* in_sizes, int n_in,
                              void* d_out, int out_size)
{
    const int*     qid_item = (const int*)    d_in[0];   // (B,1)
    const int*     qid_cate = (const int*)    d_in[1];   // (B,1)
    const int*     sid_item = (const int*)    d_in[2];   // (B,1,L)
    const int*     sid_cate = (const int*)    d_in[3];   // (B,1,L)
    const int*     mask     = (const int*)    d_in[4];   // (B,1,L) bool widened to 4B
    const float*   emb_item = (const float*)  d_in[5];   // (V,D)
    const float*   emb_cate = (const float*)  d_in[6];   // (V,D)
    const float*   W_hide   = (const float*)  d_in[7];   // (384,256)
    const float*   b_hide   = (const float*)  d_in[8];   // (256,)
    const float*   W_out    = (const float*)  d_in[9];   // (256,1)
    const float*   b_out    = (const float*)  d_in[10];  // (1,)
    float*         out      = (float*)        d_out;     // (B,1,E)

    const int B = in_sizes[0];   // 4096

    cudaFuncSetAttribute(din_fused_kernel,
                         cudaFuncAttributeMaxDynamicSharedMemorySize, SMEM_BYTES);

    din_fused_kernel<<<B, NT, SMEM_BYTES>>>(
        qid_item, qid_cate, sid_item, sid_cate, mask,
        emb_item, emb_cate, W_hide, b_hide, W_out, b_out, out);
}

// round 4
// speedup vs baseline: 1.2089x; 1.2089x over previous
#include <cuda_runtime.h>
#include <cstdint>

#define LL   50      // sequence length
#define DD   64      // per-table embedding dim
#define EE   128     // concat embedding dim (2*DD)
#define UU   256     // hidden units
#define NT   512     // threads per CTA

// packed f32x2 helpers (sm_103a; ptxas never emits FFMA2 from C++)
#define FFMA2(acc, w, k) asm("fma.rn.f32x2 %0, %1, %2, %0;" : "+l"(acc) : "l"(w), "l"(k))
#define PACK2(dst, f)    asm("mov.b64 %0, {%1, %1};" : "=l"(dst) : "r"(__float_as_uint(f)))
#define UNPK2(lo, hi, s) do { unsigned _ulo, _uhi; \
    asm("mov.b64 {%0, %1}, %2;" : "=r"(_ulo), "=r"(_uhi) : "l"(s)); \
    lo = __uint_as_float(_ulo); hi = __uint_as_float(_uhi); } while (0)

// smem floats: sW2q 32768 | sk 6400 | sq 128 | sAbh 256 | sAq 2048 | sWout 256 | sscore 64
#define SMEM_FLOATS (32768 + 6400 + 128 + 256 + 2048 + 256 + 64)
#define SMEM_BYTES  (SMEM_FLOATS*4 + 64*4)

extern "C" __global__ void __launch_bounds__(NT, 1)
din_fused_kernel(const int*   __restrict__ qid_item,
                 const int*   __restrict__ qid_cate,
                 const int*   __restrict__ sid_item,
                 const int*   __restrict__ sid_cate,
                 const int*   __restrict__ mask,    // bool widened to 4B; nonzero == true
                 const float* __restrict__ emb_item,
                 const float* __restrict__ emb_cate,
                 const float* __restrict__ W_hide,
                 const float* __restrict__ b_hide,
                 const float* __restrict__ W_out,
                 const float* __restrict__ b_out,
                 float*       __restrict__ out)
{
    extern __shared__ float smem[];
    float* sW2q   = smem;                  // [128][256] folded weight
    float* sk     = sW2q + 32768;          // [50][128]
    float* sq     = sk   + 6400;           // [128]
    float* sAbh   = sq   + 128;            // [256]
    float* sAq    = sAbh + 256;            // [8][256] strip partials
    float* sWout  = sAq  + 2048;           // [256]
    float* sscore = sWout+ 256;            // [64]
    int*   sactive= (int*)(sscore + 64);   // [56]
    int*   scnt   = sactive + 56;          // [2]

    const int b    = blockIdx.x;
    const int tid  = threadIdx.x;
    const int warp = tid >> 5;
    const int lane = tid & 31;

    // ---------------- Phase 1: gathers + ballot compaction ------------------
    unsigned bal = 0; bool act = false;
    if (warp < 2) {
        const int l = (warp << 5) + lane;
        act = (l < LL) && (mask[(size_t)b*LL + l] != 0);
        bal = __ballot_sync(0xffffffffu, act);
        if (lane == 0) scnt[warp] = __popc(bal);
    }
    if (tid < EE) {
        const int qi = qid_item[b];
        const int qc = qid_cate[b];
        sq[tid] = (tid < DD) ? emb_item[(size_t)qi*DD + tid]
                             : emb_cate[(size_t)qc*DD + (tid - DD)];
    }
    if (tid < UU) sWout[tid] = W_out[tid];
    // K gather, float4: 50*32 float4 cells
    for (int idx = tid; idx < LL*32; idx += NT) {
        const int l  = idx >> 5;
        const int e4 = idx & 31;
        float4 v;
        if (e4 < 16) v = *(const float4*)(emb_item + (size_t)sid_item[(size_t)b*LL + l]*DD + (e4 << 2));
        else         v = *(const float4*)(emb_cate + (size_t)sid_cate[(size_t)b*LL + l]*DD + ((e4 - 16) << 2));
        *(float4*)(sk + (l << 7) + (e4 << 2)) = v;
    }
    __syncthreads();

    // compaction write (deterministic order via ballot prefix)
    if (warp < 2 && act) {
        const int off = (warp == 1) ? scnt[0] : 0;
        sactive[off + __popc(bal & ((1u << lane) - 1u))] = (warp << 5) + lane;
    }

    // ---------------- Phase 2: fold W2q = Wk + q*Wp; Aq partials -------------
    {
        const int u     = (tid & 63) << 2;   // 4 consecutive u
        const int strip = tid >> 6;          // 0..7
        const int d0    = strip << 4;        // 16 d-rows per strip
        float4 aq = make_float4(0.f, 0.f, 0.f, 0.f);
        #pragma unroll 4
        for (int i = 0; i < 16; i++) {
            const int d = d0 + i;
            const float qd = sq[d];
            const float4 wk = *(const float4*)(W_hide + (size_t)(128 + d)*UU + u);
            const float4 wp = *(const float4*)(W_hide + (size_t)(256 + d)*UU + u);
            const float4 wq = *(const float4*)(W_hide + (size_t)d*UU + u);
            float4 w2;
            w2.x = fmaf(qd, wp.x, wk.x);
            w2.y = fmaf(qd, wp.y, wk.y);
            w2.z = fmaf(qd, wp.z, wk.z);
            w2.w = fmaf(qd, wp.w, wk.w);
            *(float4*)(sW2q + (d << 8) + u) = w2;
            aq.x = fmaf(qd, wq.x, aq.x);
            aq.y = fmaf(qd, wq.y, aq.y);
            aq.z = fmaf(qd, wq.z, aq.z);
            aq.w = fmaf(qd, wq.w, aq.w);
        }
        *(float4*)(sAq + strip*UU + u) = aq;
    }
    __syncthreads();
    if (tid < UU) {
        float a = b_hide[tid];
        #pragma unroll
        for (int s = 0; s < 8; s++) a += sAq[s*UU + tid];
        sAbh[tid] = a;
    }
    __syncthreads();

    // ---------------- Phase 3: mainloop (4 l's per warp, packed f32x2) -------
    const int nact  = scnt[0] + scnt[1];
    const int tiles = (nact + 3) >> 2;

    if (warp < tiles) {
        const int i0 = warp << 2;
        int nl = nact - i0; if (nl > 4) nl = 4;
        const int l0 = sactive[i0];
        const int l1 = sactive[(nl > 1) ? i0 + 1 : i0];
        const int l2 = sactive[(nl > 2) ? i0 + 2 : i0];
        const int l3 = sactive[(nl > 3) ? i0 + 3 : i0];
        const float* k0 = sk + (l0 << 7);
        const float* k1 = sk + (l1 << 7);
        const float* k2 = sk + (l2 << 7);
        const float* k3 = sk + (l3 << 7);

        const int ub = lane << 3;   // 8 hidden units per lane (4 packed pairs)
        const unsigned long long* ab = (const unsigned long long*)(sAbh + ub);
        const unsigned long long i00 = ab[0], i01 = ab[1], i02 = ab[2], i03 = ab[3];
        unsigned long long A00=i00, A01=i01, A02=i02, A03=i03;
        unsigned long long A10=i00, A11=i01, A12=i02, A13=i03;
        unsigned long long A20=i00, A21=i01, A22=i02, A23=i03;
        unsigned long long A30=i00, A31=i01, A32=i02, A33=i03;

        #pragma unroll 2
        for (int d = 0; d < EE; d++) {
            const ulonglong2* w = (const ulonglong2*)(sW2q + (d << 8) + ub);
            const ulonglong2 wA = w[0];
            const ulonglong2 wB = w[1];
            unsigned long long kp0, kp1, kp2, kp3;
            PACK2(kp0, k0[d]); PACK2(kp1, k1[d]); PACK2(kp2, k2[d]); PACK2(kp3, k3[d]);
            FFMA2(A00, wA.x, kp0); FFMA2(A01, wA.y, kp0); FFMA2(A02, wB.x, kp0); FFMA2(A03, wB.y, kp0);
            FFMA2(A10, wA.x, kp1); FFMA2(A11, wA.y, kp1); FFMA2(A12, wB.x, kp1); FFMA2(A13, wB.y, kp1);
            FFMA2(A20, wA.x, kp2); FFMA2(A21, wA.y, kp2); FFMA2(A22, wB.x, kp2); FFMA2(A23, wB.y, kp2);
            FFMA2(A30, wA.x, kp3); FFMA2(A31, wA.y, kp3); FFMA2(A32, wB.x, kp3); FFMA2(A33, wB.y, kp3);
        }

        // relu + W_out dot
        float s0 = 0.f, s1 = 0.f, s2 = 0.f, s3 = 0.f;
        const float w0 = sWout[ub+0], w1 = sWout[ub+1], w2_ = sWout[ub+2], w3 = sWout[ub+3];
        const float w4 = sWout[ub+4], w5 = sWout[ub+5], w6 = sWout[ub+6], w7 = sWout[ub+7];
        float lo, hi;
        UNPK2(lo, hi, A00); s0 += fmaxf(lo,0.f)*w0 + fmaxf(hi,0.f)*w1;
        UNPK2(lo, hi, A01); s0 += fmaxf(lo,0.f)*w2_+ fmaxf(hi,0.f)*w3;
        UNPK2(lo, hi, A02); s0 += fmaxf(lo,0.f)*w4 + fmaxf(hi,0.f)*w5;
        UNPK2(lo, hi, A03); s0 += fmaxf(lo,0.f)*w6 + fmaxf(hi,0.f)*w7;
        UNPK2(lo, hi, A10); s1 += fmaxf(lo,0.f)*w0 + fmaxf(hi,0.f)*w1;
        UNPK2(lo, hi, A11); s1 += fmaxf(lo,0.f)*w2_+ fmaxf(hi,0.f)*w3;
        UNPK2(lo, hi, A12); s1 += fmaxf(lo,0.f)*w4 + fmaxf(hi,0.f)*w5;
        UNPK2(lo, hi, A13); s1 += fmaxf(lo,0.f)*w6 + fmaxf(hi,0.f)*w7;
        UNPK2(lo, hi, A20); s2 += fmaxf(lo,0.f)*w0 + fmaxf(hi,0.f)*w1;
        UNPK2(lo, hi, A21); s2 += fmaxf(lo,0.f)*w2_+ fmaxf(hi,0.f)*w3;
        UNPK2(lo, hi, A22); s2 += fmaxf(lo,0.f)*w4 + fmaxf(hi,0.f)*w5;
        UNPK2(lo, hi, A23); s2 += fmaxf(lo,0.f)*w6 + fmaxf(hi,0.f)*w7;
        UNPK2(lo, hi, A30); s3 += fmaxf(lo,0.f)*w0 + fmaxf(hi,0.f)*w1;
        UNPK2(lo, hi, A31); s3 += fmaxf(lo,0.f)*w2_+ fmaxf(hi,0.f)*w3;
        UNPK2(lo, hi, A32); s3 += fmaxf(lo,0.f)*w4 + fmaxf(hi,0.f)*w5;
        UNPK2(lo, hi, A33); s3 += fmaxf(lo,0.f)*w6 + fmaxf(hi,0.f)*w7;

        #pragma unroll
        for (int off = 16; off > 0; off >>= 1) {
            s0 += __shfl_xor_sync(0xffffffffu, s0, off);
            s1 += __shfl_xor_sync(0xffffffffu, s1, off);
            s2 += __shfl_xor_sync(0xffffffffu, s2, off);
            s3 += __shfl_xor_sync(0xffffffffu, s3, off);
        }
        if (lane == 0) {
            const float bo = b_out[0];
            sscore[i0] = s0 + bo;
            if (nl > 1) sscore[i0 + 1] = s1 + bo;
            if (nl > 2) sscore[i0 + 2] = s2 + bo;
            if (nl > 3) sscore[i0 + 3] = s3 + bo;
        }
    }
    __syncthreads();

    // ---------------- Phase 4: deterministic weighted sum + store ------------
    if (tid < EE) {
        float acc = 0.f;
        for (int i = 0; i < nact; i++)
            acc = fmaf(sscore[i], sk[(sactive[i] << 7) + tid], acc);
        out[(size_t)b*EE + tid] = acc;
    }
}

extern "C" void kernel_launch(void* const* d_in, const int* in_sizes, int n_in,
                              void* d_out, int out_size)
{
    const int*   qid_item = (const int*)  d_in[0];
    const int*   qid_cate = (const int*)  d_in[1];
    const int*   sid_item = (const int*)  d_in[2];
    const int*   sid_cate = (const int*)  d_in[3];
    const int*   mask     = (const int*)  d_in[4];
    const float* emb_item = (const float*)d_in[5];
    const float* emb_cate = (const float*)d_in[6];
    const float* W_hide   = (const float*)d_in[7];
    const float* b_hide   = (const float*)d_in[8];
    const float* W_out    = (const float*)d_in[9];
    const float* b_out    = (const float*)d_in[10];
    float*       out      = (float*)      d_out;

    const int B = in_sizes[0];

    cudaFuncSetAttribute(din_fused_kernel,
                         cudaFuncAttributeMaxDynamicSharedMemorySize, SMEM_BYTES);

    din_fused_kernel<<<B, NT, SMEM_BYTES>>>(
        qid_item, qid_cate, sid_item, sid_cate, mask,
        emb_item, emb_cate, W_hide, b_hide, W_out, b_out, out);
}

// round 5
// speedup vs baseline: 1.3410x; 1.1092x over previous
#include <cuda_runtime.h>
#include <cstdint>

#define LL   50      // sequence length
#define DD   64      // per-table embedding dim
#define EE   128     // concat embedding dim (2*DD)
#define UU   256     // hidden units
#define NT   512     // threads per CTA

// packed f32x2 helpers (sm_103a; ptxas never emits FFMA2 from C++)
#define FFMA2(acc, w, k) asm("fma.rn.f32x2 %0, %1, %2, %0;" : "+l"(acc) : "l"(w), "l"(k))
#define PACK2(dst, f)    asm("mov.b64 %0, {%1, %1};" : "=l"(dst) : "r"(__float_as_uint(f)))
#define UNPK2(lo, hi, s) do { unsigned _ulo, _uhi; \
    asm("mov.b64 {%0, %1}, %2;" : "=r"(_ulo), "=r"(_uhi) : "l"(s)); \
    lo = __uint_as_float(_ulo); hi = __uint_as_float(_uhi); } while (0)

// smem floats: sW2q 32768 | sk 6400 | sq 128 | sAbh 256 | sAq 2048 | sWout 256 | sscore 64
#define SMEM_FLOATS (32768 + 6400 + 128 + 256 + 2048 + 256 + 64)
#define SMEM_BYTES  (SMEM_FLOATS*4 + 64*4)

extern "C" __global__ void __launch_bounds__(NT, 1)
din_fused_kernel(const int*   __restrict__ qid_item,
                 const int*   __restrict__ qid_cate,
                 const int*   __restrict__ sid_item,
                 const int*   __restrict__ sid_cate,
                 const int*   __restrict__ mask,    // bool widened to 4B; nonzero == true
                 const float* __restrict__ emb_item,
                 const float* __restrict__ emb_cate,
                 const float* __restrict__ W_hide,
                 const float* __restrict__ b_hide,
                 const float* __restrict__ W_out,
                 const float* __restrict__ b_out,
                 float*       __restrict__ out)
{
    extern __shared__ float smem[];
    float* sW2q   = smem;                  // [128][256] folded weight
    float* sk     = sW2q + 32768;          // [50][128]
    float* sq     = sk   + 6400;           // [128]
    float* sAbh   = sq   + 128;            // [256]
    float* sAq    = sAbh + 256;            // [8][256] strip partials
    float* sWout  = sAq  + 2048;           // [256]
    float* sscore = sWout+ 256;            // [64]
    int*   sactive= (int*)(sscore + 64);   // [56]
    int*   scnt   = sactive + 56;          // [2]

    const int b    = blockIdx.x;
    const int tid  = threadIdx.x;
    const int warp = tid >> 5;
    const int lane = tid & 31;

    // ---------------- Phase 1: gathers + ballot compaction ------------------
    unsigned bal = 0; bool act = false;
    if (warp < 2) {
        const int l = (warp << 5) + lane;
        act = (l < LL) && (mask[(size_t)b*LL + l] != 0);
        bal = __ballot_sync(0xffffffffu, act);
        if (lane == 0) scnt[warp] = __popc(bal);
    }
    if (tid < EE) {
        const int qi = qid_item[b];
        const int qc = qid_cate[b];
        sq[tid] = (tid < DD) ? emb_item[(size_t)qi*DD + tid]
                             : emb_cate[(size_t)qc*DD + (tid - DD)];
    }
    if (tid < UU) sWout[tid] = W_out[tid];
    // K gather, float4: 50*32 float4 cells
    for (int idx = tid; idx < LL*32; idx += NT) {
        const int l  = idx >> 5;
        const int e4 = idx & 31;
        float4 v;
        if (e4 < 16) v = *(const float4*)(emb_item + (size_t)sid_item[(size_t)b*LL + l]*DD + (e4 << 2));
        else         v = *(const float4*)(emb_cate + (size_t)sid_cate[(size_t)b*LL + l]*DD + ((e4 - 16) << 2));
        *(float4*)(sk + (l << 7) + (e4 << 2)) = v;
    }
    __syncthreads();

    // compaction write (deterministic order via ballot prefix)
    if (warp < 2 && act) {
        const int off = (warp == 1) ? scnt[0] : 0;
        sactive[off + __popc(bal & ((1u << lane) - 1u))] = (warp << 5) + lane;
    }

    // ---------------- Phase 2: fold W2q = Wk + q*Wp; Aq partials -------------
    {
        const int u     = (tid & 63) << 2;   // 4 consecutive u
        const int strip = tid >> 6;          // 0..7
        const int d0    = strip << 4;        // 16 d-rows per strip
        float4 aq = make_float4(0.f, 0.f, 0.f, 0.f);
        #pragma unroll 4
        for (int i = 0; i < 16; i++) {
            const int d = d0 + i;
            const float qd = sq[d];
            const float4 wk = *(const float4*)(W_hide + (size_t)(128 + d)*UU + u);
            const float4 wp = *(const float4*)(W_hide + (size_t)(256 + d)*UU + u);
            const float4 wq = *(const float4*)(W_hide + (size_t)d*UU + u);
            float4 w2;
            w2.x = fmaf(qd, wp.x, wk.x);
            w2.y = fmaf(qd, wp.y, wk.y);
            w2.z = fmaf(qd, wp.z, wk.z);
            w2.w = fmaf(qd, wp.w, wk.w);
            *(float4*)(sW2q + (d << 8) + u) = w2;
            aq.x = fmaf(qd, wq.x, aq.x);
            aq.y = fmaf(qd, wq.y, aq.y);
            aq.z = fmaf(qd, wq.z, aq.z);
            aq.w = fmaf(qd, wq.w, aq.w);
        }
        *(float4*)(sAq + strip*UU + u) = aq;
    }
    __syncthreads();
    if (tid < UU) {
        float a = b_hide[tid];
        #pragma unroll
        for (int s = 0; s < 8; s++) a += sAq[s*UU + tid];
        sAbh[tid] = a;
    }
    __syncthreads();

    // ---------------- Phase 3: mainloop (8 l's per warp, packed f32x2) -------
    const int nact  = scnt[0] + scnt[1];
    const int tiles = (nact + 7) >> 3;

    if (warp < tiles) {
        const int i0 = warp << 3;
        int nl = nact - i0; if (nl > 8) nl = 8;

        int koff[8];
        #pragma unroll
        for (int t = 0; t < 8; t++)
            koff[t] = sactive[(t < nl) ? i0 + t : i0] << 7;

        const int ub = lane << 3;   // 8 hidden units per lane (4 packed pairs)
        const unsigned long long* ab = (const unsigned long long*)(sAbh + ub);
        const unsigned long long i00 = ab[0], i01 = ab[1], i02 = ab[2], i03 = ab[3];
        unsigned long long A[8][4];
        #pragma unroll
        for (int t = 0; t < 8; t++) { A[t][0]=i00; A[t][1]=i01; A[t][2]=i02; A[t][3]=i03; }

        for (int d0 = 0; d0 < EE; d0 += 4) {
            float4 kv[8];
            #pragma unroll
            for (int t = 0; t < 8; t++)
                kv[t] = *(const float4*)(sk + koff[t] + d0);   // broadcast LDS.128 (1 wf)

            #pragma unroll
            for (int dd = 0; dd < 4; dd++) {
                const ulonglong2* w = (const ulonglong2*)(sW2q + ((d0 + dd) << 8) + ub);
                const ulonglong2 wA = w[0];
                const ulonglong2 wB = w[1];
                #pragma unroll
                for (int t = 0; t < 8; t++) {
                    unsigned long long kp;
                    PACK2(kp, ((const float*)&kv[t])[dd]);
                    FFMA2(A[t][0], wA.x, kp);
                    FFMA2(A[t][1], wA.y, kp);
                    FFMA2(A[t][2], wB.x, kp);
                    FFMA2(A[t][3], wB.y, kp);
                }
            }
        }

        // relu + W_out dot, per-lane partial over its 8 units
        const float w0 = sWout[ub+0], w1 = sWout[ub+1], w2_ = sWout[ub+2], w3 = sWout[ub+3];
        const float w4 = sWout[ub+4], w5 = sWout[ub+5], w6 = sWout[ub+6], w7 = sWout[ub+7];
        float s[8];
        #pragma unroll
        for (int t = 0; t < 8; t++) {
            float lo, hi, acc;
            UNPK2(lo, hi, A[t][0]); acc  = fmaxf(lo,0.f)*w0 + fmaxf(hi,0.f)*w1;
            UNPK2(lo, hi, A[t][1]); acc += fmaxf(lo,0.f)*w2_+ fmaxf(hi,0.f)*w3;
            UNPK2(lo, hi, A[t][2]); acc += fmaxf(lo,0.f)*w4 + fmaxf(hi,0.f)*w5;
            UNPK2(lo, hi, A[t][3]); acc += fmaxf(lo,0.f)*w6 + fmaxf(hi,0.f)*w7;
            s[t] = acc;
        }
        #pragma unroll
        for (int t = 0; t < 8; t++) {
            #pragma unroll
            for (int off = 16; off > 0; off >>= 1)
                s[t] += __shfl_xor_sync(0xffffffffu, s[t], off);
        }
        if (lane == 0) {
            const float bo = b_out[0];
            #pragma unroll
            for (int t = 0; t < 8; t++)
                if (t < nl) sscore[i0 + t] = s[t] + bo;
        }
    }
    __syncthreads();

    // ---------------- Phase 4: deterministic weighted sum + store ------------
    if (tid < EE) {
        float acc = 0.f;
        for (int i = 0; i < nact; i++)
            acc = fmaf(sscore[i], sk[(sactive[i] << 7) + tid], acc);
        out[(size_t)b*EE + tid] = acc;
    }
}

extern "C" void kernel_launch(void* const* d_in, const int* in_sizes, int n_in,
                              void* d_out, int out_size)
{
    const int*   qid_item = (const int*)  d_in[0];
    const int*   qid_cate = (const int*)  d_in[1];
    const int*   sid_item = (const int*)  d_in[2];
    const int*   sid_cate = (const int*)  d_in[3];
    const int*   mask     = (const int*)  d_in[4];
    const float* emb_item = (const float*)d_in[5];
    const float* emb_cate = (const float*)d_in[6];
    const float* W_hide   = (const float*)d_in[7];
    const float* b_hide   = (const float*)d_in[8];
    const float* W_out    = (const float*)d_in[9];
    const float* b_out    = (const float*)d_in[10];
    float*       out      = (float*)      d_out;

    const int B = in_sizes[0];

    cudaFuncSetAttribute(din_fused_kernel,
                         cudaFuncAttributeMaxDynamicSharedMemorySize, SMEM_BYTES);

    din_fused_kernel<<<B, NT, SMEM_BYTES>>>(
        qid_item, qid_cate, sid_item, sid_cate, mask,
        emb_item, emb_cate, W_hide, b_hide, W_out, b_out, out);
}